// round 13
// baseline (speedup 1.0000x reference)
#include <cuda_runtime.h>

// R2D2Head fused, 4 CTAs/SM: B tasks, s=25, d=640, 5-way, q=75
#define NS 25
#define DQ 640
#define NWAY 5
#define NQ 75
#define RIDGE 50.0f

#define HD 320      // d-half width
#define HSR 320     // S-half smem row stride
#define ACOLS 33    // augmented matrix row stride (conflict-free columns)
#define WS 640      // W_T smem row stride

// shared memory layout (floats)
#define OFF_S    0          // 25*320 = 8000 (staged half of S)
#define OFF_A    8000       // 25*33 = 825
#define OFF_SOL  8828       // 200
#define OFF_WT   9028       // 5*640 = 3200
#define OFF_LOG  12228      // 376
#define OFF_FLAG 12604      // 4
#define SMEM_FLOATS 12608   // 50432 B -> 4 CTAs/SM

__global__ __launch_bounds__(256, 4)
void r2d2_fused(const float* __restrict__ query,
                const float* __restrict__ support,
                const int* __restrict__ labels_raw,
                float* __restrict__ out)
{
    extern __shared__ float sm[];
    float* Ssm = sm + OFF_S;
    float* A   = sm + OFF_A;
    float* SOL = sm + OFF_SOL;
    float* WT  = sm + OFF_WT;
    float* LOG = sm + OFF_LOG;
    int*  FLAG = (int*)(sm + OFF_FLAG);

    const int b = blockIdx.x;
    const int t = threadIdx.x;
    const int warp = t >> 5, lane = t & 31;

    // ---- Phase 0: label dtype sniff (parallel, one load latency) ----
    if (warp == 0) {
        int lo = labels_raw[2 * lane];
        int hi = labels_raw[2 * lane + 1];
        bool ok = (hi == 0) && (lo >= 0) && (lo <= 4);
        unsigned m = __ballot_sync(0xffffffffu, ok);
        if (lane == 0) FLAG[0] = (m == 0xffffffffu) ? 1 : 0;
    }

    const float4* Sg4 = (const float4*)(support + (size_t)b * NS * DQ);

    // ---- Phase 1+2: gram over two S-half stagings ----
    for (int h = 0; h < 2; ++h) {
        __syncthreads();                 // protect prior pass reads
        {
            float4* Ss4 = (float4*)Ssm;
            for (int idx = t; idx < NS * HD / 4; idx += 256) {
                int row = idx / (HD / 4);
                int c4  = idx - row * (HD / 4);
                Ss4[idx] = Sg4[row * (DQ / 4) + h * (HD / 4) + c4];
            }
        }
        __syncthreads();

        // warp per 5x5 triangular tile; fp32 register tile; merge into A
        for (int tile = warp; tile < 15; tile += 8) {
            int ti = 0, rem = tile;
            while (rem >= 5 - ti) { rem -= 5 - ti; ++ti; }
            int tj = ti + rem;

            float acc[5][5];
            #pragma unroll
            for (int r = 0; r < 5; ++r)
                #pragma unroll
                for (int c = 0; c < 5; ++c) acc[r][c] = 0.f;

            const float* Ri = Ssm + (5 * ti) * HSR;
            const float* Rj = Ssm + (5 * tj) * HSR;
            #pragma unroll 2
            for (int it = 0; it < 10; ++it) {     // 10*32 = 320
                int d = lane + it * 32;
                float av[5], bv[5];
                #pragma unroll
                for (int r = 0; r < 5; ++r) av[r] = Ri[r * HSR + d];
                #pragma unroll
                for (int c = 0; c < 5; ++c) bv[c] = Rj[c * HSR + d];
                #pragma unroll
                for (int r = 0; r < 5; ++r)
                    #pragma unroll
                    for (int c = 0; c < 5; ++c)
                        acc[r][c] = fmaf(av[r], bv[c], acc[r][c]);
            }
            #pragma unroll
            for (int r = 0; r < 5; ++r)
                #pragma unroll
                for (int c = 0; c < 5; ++c) {
                    float v = acc[r][c];
                    v += __shfl_down_sync(0xffffffffu, v, 16);
                    v += __shfl_down_sync(0xffffffffu, v, 8);
                    v += __shfl_down_sync(0xffffffffu, v, 4);
                    v += __shfl_down_sync(0xffffffffu, v, 2);
                    v += __shfl_down_sync(0xffffffffu, v, 1);
                    if (lane == 0) {
                        int i = 5 * ti + r, j = 5 * tj + c;
                        // FIX (R12 bug): canonicalize to i <= j. Diagonal
                        // tiles compute (r,c) AND (c,r); merging both in the
                        // h=1 pass double-added the second-half contribution.
                        if (i <= j) {
                            if (h == 0) {
                                float g = v + (i == j ? RIDGE : 0.f);
                                A[i * ACOLS + j] = g;
                                if (i != j) A[j * ACOLS + i] = g;
                            } else {
                                float g = A[i * ACOLS + j] + v;
                                A[i * ACOLS + j] = g;
                                if (i != j) A[j * ACOLS + i] = g;
                            }
                        }
                    }
                }
        }
    }

    const int lab_i64 = FLAG[0];
    if (t < 125) {                               // one-hot Y cols 25..29
        int i = t / 5, w = t - i * 5;
        int base = b * NS + i;
        int lab = lab_i64 ? labels_raw[2 * base] : labels_raw[base];
        A[i * ACOLS + 25 + w] = (lab == w) ? 1.f : 0.f;
    }
    __syncthreads();

    // ---- Phase 3: block-parallel Gauss-Jordan (SPD + ridge), fast div ----
    {
        const int gi = t % 25;
        const int gj = t / 25;
        const bool act = (t < 250);
        for (int k = 0; k < NS; ++k) {
            float f = 0.f, pk0 = 0.f, pk1 = 0.f, pk2 = 0.f;
            if (act) {
                f   = __fdividef(A[gi * ACOLS + k], A[k * ACOLS + k]);
                pk0 = A[k * ACOLS + gj];
                pk1 = A[k * ACOLS + gj + 10];
                pk2 = A[k * ACOLS + gj + 20];
            }
            __syncthreads();
            if (act && gi != k) {
                A[gi * ACOLS + gj]      -= f * pk0;
                A[gi * ACOLS + gj + 10] -= f * pk1;
                A[gi * ACOLS + gj + 20] -= f * pk2;
            }
            __syncthreads();
        }
    }
    if (t < 125) {
        int i = t / 5, w = t - i * 5;
        SOL[i * 8 + w] = __fdividef(A[i * ACOLS + 25 + w], A[i * ACOLS + i]);
    }

    // ---- Phase 4: W per half (re-stage S halves; 2nd read L2-hot) ----
    for (int h = 0; h < 2; ++h) {
        __syncthreads();                 // prior reads of Ssm / solve done
        {
            float4* Ss4 = (float4*)Ssm;
            for (int idx = t; idx < NS * HD / 4; idx += 256) {
                int row = idx / (HD / 4);
                int c4  = idx - row * (HD / 4);
                Ss4[idx] = Sg4[row * (DQ / 4) + h * (HD / 4) + c4];
            }
        }
        __syncthreads();

        int d0 = t;                       // 0..255
        int d1 = t + 256;                 // valid for t < 64
        bool h1v = (d1 < HD);
        float a0[5], a1[5];
        #pragma unroll
        for (int w = 0; w < 5; ++w) { a0[w] = 0.f; a1[w] = 0.f; }
        for (int s = 0; s < NS; ++s) {
            float s0 = Ssm[s * HSR + d0];
            float s1 = h1v ? Ssm[s * HSR + d1] : 0.f;
            #pragma unroll
            for (int w = 0; w < 5; ++w) {
                float sv = SOL[s * 8 + w];
                a0[w] = fmaf(s0, sv, a0[w]);
                a1[w] = fmaf(s1, sv, a1[w]);
            }
        }
        #pragma unroll
        for (int w = 0; w < 5; ++w) {
            WT[w * WS + h * HD + d0] = a0[w];
            if (h1v) WT[w * WS + h * HD + d1] = a1[w];
        }
    }
    __syncthreads();

    // ---- Phase 5: logits = Q @ W, warp per 5 query rows, float4 streams ----
    const float4* Qb = (const float4*)(query + (size_t)b * NQ * DQ);
    for (int g = warp; g < 15; g += 8) {
        int r0 = g * 5;
        float acc[5][5];
        #pragma unroll
        for (int r = 0; r < 5; ++r)
            #pragma unroll
            for (int w = 0; w < 5; ++w) acc[r][w] = 0.f;

        #pragma unroll
        for (int it = 0; it < 5; ++it) {
            int d4 = lane + it * 32;
            float4 qv[5];
            #pragma unroll
            for (int r = 0; r < 5; ++r) qv[r] = __ldcs(&Qb[(r0 + r) * 160 + d4]);
            #pragma unroll
            for (int w = 0; w < 5; ++w) {
                float4 wv = *(const float4*)&WT[w * WS + d4 * 4];
                #pragma unroll
                for (int r = 0; r < 5; ++r) {
                    acc[r][w] = fmaf(qv[r].x, wv.x, acc[r][w]);
                    acc[r][w] = fmaf(qv[r].y, wv.y, acc[r][w]);
                    acc[r][w] = fmaf(qv[r].z, wv.z, acc[r][w]);
                    acc[r][w] = fmaf(qv[r].w, wv.w, acc[r][w]);
                }
            }
        }
        #pragma unroll
        for (int r = 0; r < 5; ++r)
            #pragma unroll
            for (int w = 0; w < 5; ++w) {
                float v = acc[r][w];
                v += __shfl_xor_sync(0xffffffffu, v, 16);
                v += __shfl_xor_sync(0xffffffffu, v, 8);
                v += __shfl_xor_sync(0xffffffffu, v, 4);
                v += __shfl_xor_sync(0xffffffffu, v, 2);
                v += __shfl_xor_sync(0xffffffffu, v, 1);
                acc[r][w] = v;
            }
        if (lane == 0) {
            #pragma unroll
            for (int r = 0; r < 5; ++r)
                #pragma unroll
                for (int w = 0; w < 5; ++w)
                    LOG[(r0 + r) * 5 + w] = acc[r][w];
        }
    }
    __syncthreads();

    // ---- Phase 6: coalesced output store ----
    for (int idx = t; idx < NQ * NWAY; idx += 256)
        out[(size_t)b * (NQ * NWAY) + idx] = LOG[idx];
}

extern "C" void kernel_launch(void* const* d_in, const int* in_sizes, int n_in,
                              void* d_out, int out_size)
{
    const float* query   = (const float*)d_in[0];
    const float* support = (const float*)d_in[1];
    const int* labels    = (const int*)d_in[2];
    float* out = (float*)d_out;

    int tasks = in_sizes[1] / (NS * DQ);   // 2048

    size_t smem = (size_t)SMEM_FLOATS * sizeof(float);
    cudaFuncSetAttribute(r2d2_fused,
                         cudaFuncAttributeMaxDynamicSharedMemorySize, (int)smem);

    r2d2_fused<<<tasks, 256, smem>>>(query, support, labels, out);
}

// round 14
// speedup vs baseline: 1.3200x; 1.3200x over previous
#include <cuda_runtime.h>

// R2D2Head fused (R11 base + cp.async staging + ping-pong solve)
#define NS 25
#define DQ 640
#define NWAY 5
#define NQ 75
#define RIDGE 50.0f

#define SR 640     // S smem row stride
#define ACOLS 33   // augmented matrix row stride (conflict-free columns)
#define WS 640     // W_T smem row stride (reuses front of S region)

// shared memory layout (floats)
#define OFF_S    0          // 25*640 = 16000 ; front reused as WT in B-phase
#define OFF_A0   16000      // 25*33 = 825
#define OFF_A1   16828      // 825 (ping-pong buffer)
#define OFF_SOL  17656      // 200
#define OFF_LOG  17856      // 376
#define OFF_FLAG 18232      // 4
#define SMEM_FLOATS 18240   // 72960 B -> 3 CTAs/SM

// packed fp32x2 FMA (FFMA2) — only reachable via PTX
__device__ __forceinline__ void fma_f32x2(unsigned long long& acc,
                                          unsigned long long a,
                                          unsigned long long b)
{
    asm("fma.rn.f32x2 %0, %1, %2, %0;" : "+l"(acc) : "l"(a), "l"(b));
}

__global__ __launch_bounds__(256, 3)
void r2d2_fused(const float* __restrict__ query,
                const float* __restrict__ support,
                const int* __restrict__ labels_raw,
                float* __restrict__ out)
{
    extern __shared__ float sm[];
    float* Ssm = sm + OFF_S;
    float* A0  = sm + OFF_A0;
    float* A1  = sm + OFF_A1;
    float* SOL = sm + OFF_SOL;
    float* LOG = sm + OFF_LOG;
    float* WT  = sm + OFF_S;          // alias: S region reused after W phase
    int*  FLAG = (int*)(sm + OFF_FLAG);

    const int b = blockIdx.x;
    const int t = threadIdx.x;
    const int warp = t >> 5, lane = t & 31;

    // ---- Phase 0: label dtype sniff (parallel, one load latency) ----
    if (warp == 0) {
        int lo = labels_raw[2 * lane];
        int hi = labels_raw[2 * lane + 1];
        bool ok = (hi == 0) && (lo >= 0) && (lo <= 4);
        unsigned m = __ballot_sync(0xffffffffu, ok);
        if (lane == 0) FLAG[0] = (m == 0xffffffffu) ? 1 : 0;
    }

    // ---- Phase 1: S (25x640) global->smem via cp.async (one L1 transit) ----
    {
        const float4* Sg4 = (const float4*)(support + (size_t)b * NS * DQ);
        unsigned sbase = (unsigned)__cvta_generic_to_shared(Ssm);
        for (int idx = t; idx < NS * DQ / 4; idx += 256) {
            unsigned daddr = sbase + idx * 16;
            asm volatile("cp.async.cg.shared.global [%0], [%1], 16;"
                         :: "r"(daddr), "l"(Sg4 + idx));
        }
        asm volatile("cp.async.commit_group;");
        asm volatile("cp.async.wait_group 0;");
    }
    __syncthreads();

    const int lab_i64 = FLAG[0];

    // ---- Phase 2: gram, warp per 5x5 triangular tile, f32x2 FMA ----
    for (int tile = warp; tile < 15; tile += 8) {
        int ti = 0, rem = tile;
        while (rem >= 5 - ti) { rem -= 5 - ti; ++ti; }
        int tj = ti + rem;

        unsigned long long acc2[5][5];
        #pragma unroll
        for (int r = 0; r < 5; ++r)
            #pragma unroll
            for (int c = 0; c < 5; ++c) acc2[r][c] = 0ull;

        const float* Ri = Ssm + (5 * ti) * SR;
        const float* Rj = Ssm + (5 * tj) * SR;
        #pragma unroll 2
        for (int it = 0; it < 10; ++it) {      // 10 * 64 = 640
            int off = 2 * lane + 64 * it;
            unsigned long long av[5], bv[5];
            #pragma unroll
            for (int r = 0; r < 5; ++r)
                av[r] = *(const unsigned long long*)(Ri + r * SR + off);
            #pragma unroll
            for (int c = 0; c < 5; ++c)
                bv[c] = *(const unsigned long long*)(Rj + c * SR + off);
            #pragma unroll
            for (int r = 0; r < 5; ++r)
                #pragma unroll
                for (int c = 0; c < 5; ++c)
                    fma_f32x2(acc2[r][c], av[r], bv[c]);
        }
        #pragma unroll
        for (int r = 0; r < 5; ++r)
            #pragma unroll
            for (int c = 0; c < 5; ++c) {
                float2 p = *reinterpret_cast<float2*>(&acc2[r][c]);
                float v = p.x + p.y;
                v += __shfl_down_sync(0xffffffffu, v, 16);
                v += __shfl_down_sync(0xffffffffu, v, 8);
                v += __shfl_down_sync(0xffffffffu, v, 4);
                v += __shfl_down_sync(0xffffffffu, v, 2);
                v += __shfl_down_sync(0xffffffffu, v, 1);
                if (lane == 0) {
                    int i = 5 * ti + r, j = 5 * tj + c;
                    float g = v + (i == j ? RIDGE : 0.f);
                    A0[i * ACOLS + j] = g;
                    A0[j * ACOLS + i] = g;
                }
            }
    }
    if (t < 125) {                              // one-hot Y cols 25..29
        int i = t / 5, w = t - i * 5;
        int base = b * NS + i;
        int lab = lab_i64 ? labels_raw[2 * base] : labels_raw[base];
        A0[i * ACOLS + 25 + w] = (lab == w) ? 1.f : 0.f;
    }
    __syncthreads();

    // ---- Phase 3: ping-pong Gauss-Jordan — ONE barrier per pivot ----
    // iter k: read buf[k&1], write buf[(k+1)&1]; pivot row copied (f==0).
    {
        const int gi = t % 25;
        const int gj = t / 25;
        const bool act = (t < 250);
        float* bufs[2] = { A0, A1 };
        for (int k = 0; k < NS; ++k) {
            const float* src = bufs[k & 1];
            float* dst = bufs[(k + 1) & 1];
            if (act) {
                float f = (gi == k) ? 0.f
                        : __fdividef(src[gi * ACOLS + k], src[k * ACOLS + k]);
                float pk0 = src[k * ACOLS + gj];
                float pk1 = src[k * ACOLS + gj + 10];
                float pk2 = src[k * ACOLS + gj + 20];
                dst[gi * ACOLS + gj]      = src[gi * ACOLS + gj]      - f * pk0;
                dst[gi * ACOLS + gj + 10] = src[gi * ACOLS + gj + 10] - f * pk1;
                dst[gi * ACOLS + gj + 20] = src[gi * ACOLS + gj + 20] - f * pk2;
            }
            __syncthreads();
        }
    }
    // result in A1 (25 iters: final write went to bufs[25&1] = A1)
    if (t < 125) {
        int i = t / 5, w = t - i * 5;
        SOL[i * 8 + w] = __fdividef(A1[i * ACOLS + 25 + w], A1[i * ACOLS + i]);
    }
    __syncthreads();

    // ---- Phase 4: W in registers (reads all of S), then overwrite S front ----
    {
        int d0 = t, d1 = t + 256, d2 = t + 512;
        bool h2 = (d2 < DQ);                    // t < 128
        float a0[5], a1[5], a2[5];
        #pragma unroll
        for (int w = 0; w < 5; ++w) { a0[w] = 0.f; a1[w] = 0.f; a2[w] = 0.f; }
        for (int s = 0; s < NS; ++s) {
            float s0 = Ssm[s * SR + d0];
            float s1 = Ssm[s * SR + d1];
            float s2 = h2 ? Ssm[s * SR + d2] : 0.f;
            #pragma unroll
            for (int w = 0; w < 5; ++w) {
                float sv = SOL[s * 8 + w];
                a0[w] = fmaf(s0, sv, a0[w]);
                a1[w] = fmaf(s1, sv, a1[w]);
                a2[w] = fmaf(s2, sv, a2[w]);
            }
        }
        __syncthreads();                        // all S reads done before overwrite
        #pragma unroll
        for (int w = 0; w < 5; ++w) {
            WT[w * WS + d0] = a0[w];
            WT[w * WS + d1] = a1[w];
            if (h2) WT[w * WS + d2] = a2[w];
        }
    }
    __syncthreads();

    // ---- Phase 5: logits = Q @ W, warp per 5 query rows, float4 streams ----
    const float4* Qb = (const float4*)(query + (size_t)b * NQ * DQ);
    for (int g = warp; g < 15; g += 8) {
        int r0 = g * 5;
        float acc[5][5];
        #pragma unroll
        for (int r = 0; r < 5; ++r)
            #pragma unroll
            for (int w = 0; w < 5; ++w) acc[r][w] = 0.f;

        #pragma unroll
        for (int it = 0; it < 5; ++it) {
            int d4 = lane + it * 32;
            float4 qv[5];
            #pragma unroll
            for (int r = 0; r < 5; ++r) qv[r] = __ldcs(&Qb[(r0 + r) * 160 + d4]);
            #pragma unroll
            for (int w = 0; w < 5; ++w) {
                float4 wv = *(const float4*)&WT[w * WS + d4 * 4];
                #pragma unroll
                for (int r = 0; r < 5; ++r) {
                    acc[r][w] = fmaf(qv[r].x, wv.x, acc[r][w]);
                    acc[r][w] = fmaf(qv[r].y, wv.y, acc[r][w]);
                    acc[r][w] = fmaf(qv[r].z, wv.z, acc[r][w]);
                    acc[r][w] = fmaf(qv[r].w, wv.w, acc[r][w]);
                }
            }
        }
        #pragma unroll
        for (int r = 0; r < 5; ++r)
            #pragma unroll
            for (int w = 0; w < 5; ++w) {
                float v = acc[r][w];
                v += __shfl_xor_sync(0xffffffffu, v, 16);
                v += __shfl_xor_sync(0xffffffffu, v, 8);
                v += __shfl_xor_sync(0xffffffffu, v, 4);
                v += __shfl_xor_sync(0xffffffffu, v, 2);
                v += __shfl_xor_sync(0xffffffffu, v, 1);
                acc[r][w] = v;
            }
        if (lane == 0) {
            #pragma unroll
            for (int r = 0; r < 5; ++r)
                #pragma unroll
                for (int w = 0; w < 5; ++w)
                    LOG[(r0 + r) * 5 + w] = acc[r][w];
        }
    }
    __syncthreads();

    // ---- Phase 6: coalesced output store ----
    for (int idx = t; idx < NQ * NWAY; idx += 256)
        out[(size_t)b * (NQ * NWAY) + idx] = LOG[idx];
}

extern "C" void kernel_launch(void* const* d_in, const int* in_sizes, int n_in,
                              void* d_out, int out_size)
{
    const float* query   = (const float*)d_in[0];
    const float* support = (const float*)d_in[1];
    const int* labels    = (const int*)d_in[2];
    float* out = (float*)d_out;

    int tasks = in_sizes[1] / (NS * DQ);   // 2048

    size_t smem = (size_t)SMEM_FLOATS * sizeof(float);
    cudaFuncSetAttribute(r2d2_fused,
                         cudaFuncAttributeMaxDynamicSharedMemorySize, (int)smem);

    r2d2_fused<<<tasks, 256, smem>>>(query, support, labels, out);
}

// round 15
// speedup vs baseline: 1.3415x; 1.0162x over previous
#include <cuda_runtime.h>

// R2D2Head fused: cp.async staging + reg-resident solve + diag-reuse gram
#define NS 25
#define DQ 640
#define NWAY 5
#define NQ 75
#define RIDGE 50.0f

#define SR 640     // S smem row stride
#define ACOLS 33   // gram matrix row stride (conflict-free columns)
#define WS 640     // W_T smem row stride (reuses front of S region)

// shared memory layout (floats)
#define OFF_S    0          // 25*640 = 16000 ; front reused as WT in B-phase
#define OFF_A    16000      // 25*33 = 825 (gram + one-hot staging)
#define OFF_COLK 16828      // 2*32 = 64 (pivot column, parity buffers)
#define OFF_PROW 16892      // 2*32 = 64 (pivot row, parity buffers)
#define OFF_DIAG 16956      // 32
#define OFF_SOL  16988      // 200
#define OFF_LOG  17188      // 376
#define OFF_FLAG 17564      // 4
#define SMEM_FLOATS 17568   // 70272 B -> 3 CTAs/SM

// packed fp32x2 FMA (FFMA2) — only reachable via PTX
__device__ __forceinline__ void fma_f32x2(unsigned long long& acc,
                                          unsigned long long a,
                                          unsigned long long b)
{
    asm("fma.rn.f32x2 %0, %1, %2, %0;" : "+l"(acc) : "l"(a), "l"(b));
}

__global__ __launch_bounds__(256, 3)
void r2d2_fused(const float* __restrict__ query,
                const float* __restrict__ support,
                const int* __restrict__ labels_raw,
                float* __restrict__ out)
{
    extern __shared__ float sm[];
    float* Ssm  = sm + OFF_S;
    float* A    = sm + OFF_A;
    float* COLK = sm + OFF_COLK;
    float* PROW = sm + OFF_PROW;
    float* DIAG = sm + OFF_DIAG;
    float* SOL  = sm + OFF_SOL;
    float* LOG  = sm + OFF_LOG;
    float* WT   = sm + OFF_S;         // alias: S region reused after W phase
    int*  FLAG  = (int*)(sm + OFF_FLAG);

    const int b = blockIdx.x;
    const int t = threadIdx.x;
    const int warp = t >> 5, lane = t & 31;

    // ---- Phase 0: label dtype sniff (parallel, one load latency) ----
    if (warp == 0) {
        int lo = labels_raw[2 * lane];
        int hi = labels_raw[2 * lane + 1];
        bool ok = (hi == 0) && (lo >= 0) && (lo <= 4);
        unsigned m = __ballot_sync(0xffffffffu, ok);
        if (lane == 0) FLAG[0] = (m == 0xffffffffu) ? 1 : 0;
    }

    // ---- Phase 1: S (25x640) global->smem via cp.async ----
    {
        const float4* Sg4 = (const float4*)(support + (size_t)b * NS * DQ);
        unsigned sbase = (unsigned)__cvta_generic_to_shared(Ssm);
        for (int idx = t; idx < NS * DQ / 4; idx += 256) {
            unsigned daddr = sbase + idx * 16;
            asm volatile("cp.async.cg.shared.global [%0], [%1], 16;"
                         :: "r"(daddr), "l"(Sg4 + idx));
        }
        asm volatile("cp.async.commit_group;");
        asm volatile("cp.async.wait_group 0;");
    }
    __syncthreads();

    const int lab_i64 = FLAG[0];

    // ---- Phase 2: gram, warp per 5x5 tri tile, f32x2, diag av-reuse ----
    for (int tile = warp; tile < 15; tile += 8) {
        int ti = 0, rem = tile;
        while (rem >= 5 - ti) { rem -= 5 - ti; ++ti; }
        int tj = ti + rem;
        const bool diag = (ti == tj);

        unsigned long long acc2[5][5];
        #pragma unroll
        for (int r = 0; r < 5; ++r)
            #pragma unroll
            for (int c = 0; c < 5; ++c) acc2[r][c] = 0ull;

        const float* Ri = Ssm + (5 * ti) * SR;
        const float* Rj = Ssm + (5 * tj) * SR;
        #pragma unroll 2
        for (int it = 0; it < 10; ++it) {      // 10 * 64 = 640
            int off = 2 * lane + 64 * it;
            unsigned long long av[5], bv[5];
            #pragma unroll
            for (int r = 0; r < 5; ++r)
                av[r] = *(const unsigned long long*)(Ri + r * SR + off);
            if (!diag) {
                #pragma unroll
                for (int c = 0; c < 5; ++c)
                    bv[c] = *(const unsigned long long*)(Rj + c * SR + off);
            } else {
                #pragma unroll
                for (int c = 0; c < 5; ++c) bv[c] = av[c];
            }
            #pragma unroll
            for (int r = 0; r < 5; ++r)
                #pragma unroll
                for (int c = 0; c < 5; ++c)
                    fma_f32x2(acc2[r][c], av[r], bv[c]);
        }
        #pragma unroll
        for (int r = 0; r < 5; ++r)
            #pragma unroll
            for (int c = 0; c < 5; ++c) {
                float2 p = *reinterpret_cast<float2*>(&acc2[r][c]);
                float v = p.x + p.y;
                v += __shfl_down_sync(0xffffffffu, v, 16);
                v += __shfl_down_sync(0xffffffffu, v, 8);
                v += __shfl_down_sync(0xffffffffu, v, 4);
                v += __shfl_down_sync(0xffffffffu, v, 2);
                v += __shfl_down_sync(0xffffffffu, v, 1);
                if (lane == 0) {
                    int i = 5 * ti + r, j = 5 * tj + c;
                    float g = v + (i == j ? RIDGE : 0.f);
                    A[i * ACOLS + j] = g;
                    A[j * ACOLS + i] = g;
                }
            }
    }
    if (t < 125) {                              // one-hot Y cols 25..29
        int i = t / 5, w = t - i * 5;
        int base = b * NS + i;
        int lab = lab_i64 ? labels_raw[2 * base] : labels_raw[base];
        A[i * ACOLS + 25 + w] = (lab == w) ? 1.f : 0.f;
    }
    __syncthreads();

    // ---- Phase 3: register-resident Gauss-Jordan, 1 barrier/pivot ----
    // Thread (gi,gj) owns cols {gj, gj+10, gj+20} of row gi in registers.
    // Per iter only pivot column (25) + pivot row (30) transit smem,
    // parity-double-buffered so one barrier suffices.
    {
        const int gi = t % 25;
        const int gj = t / 25;
        const bool act = (t < 250);
        float r0 = 0.f, r1 = 0.f, r2 = 0.f;
        if (act) {
            r0 = A[gi * ACOLS + gj];
            r1 = A[gi * ACOLS + gj + 10];
            r2 = A[gi * ACOLS + gj + 20];
        }
        for (int k = 0; k < NS; ++k) {
            float* ck = COLK + (k & 1) * 32;
            float* pr = PROW + (k & 1) * 32;
            if (act) {
                if (gj == k % 10) {
                    int idx = k / 10;
                    ck[gi] = (idx == 0) ? r0 : (idx == 1) ? r1 : r2;
                }
                if (gi == k) { pr[gj] = r0; pr[gj + 10] = r1; pr[gj + 20] = r2; }
            }
            __syncthreads();
            if (act) {
                float f = (gi == k) ? 0.f : __fdividef(ck[gi], ck[k]);
                r0 = fmaf(-f, pr[gj],      r0);
                r1 = fmaf(-f, pr[gj + 10], r1);
                r2 = fmaf(-f, pr[gj + 20], r2);
            }
        }
        // extract SOL: diag from owner threads, then cols 25..29 (in r2, gj>=5)
        if (act && gj == gi % 10) {
            int idx = gi / 10;
            DIAG[gi] = (idx == 0) ? r0 : (idx == 1) ? r1 : r2;
        }
        __syncthreads();
        if (act && gj >= 5) {
            int w = gj - 5;                     // r2 = col 20+gj = 25+w
            SOL[gi * 8 + w] = __fdividef(r2, DIAG[gi]);
        }
    }
    __syncthreads();

    // ---- Phase 4: W in registers (reads all of S), then overwrite S front ----
    {
        int d0 = t, d1 = t + 256, d2 = t + 512;
        bool h2 = (d2 < DQ);                    // t < 128
        float a0[5], a1[5], a2[5];
        #pragma unroll
        for (int w = 0; w < 5; ++w) { a0[w] = 0.f; a1[w] = 0.f; a2[w] = 0.f; }
        for (int s = 0; s < NS; ++s) {
            float s0 = Ssm[s * SR + d0];
            float s1 = Ssm[s * SR + d1];
            float s2 = h2 ? Ssm[s * SR + d2] : 0.f;
            #pragma unroll
            for (int w = 0; w < 5; ++w) {
                float sv = SOL[s * 8 + w];
                a0[w] = fmaf(s0, sv, a0[w]);
                a1[w] = fmaf(s1, sv, a1[w]);
                a2[w] = fmaf(s2, sv, a2[w]);
            }
        }
        __syncthreads();                        // all S reads done before overwrite
        #pragma unroll
        for (int w = 0; w < 5; ++w) {
            WT[w * WS + d0] = a0[w];
            WT[w * WS + d1] = a1[w];
            if (h2) WT[w * WS + d2] = a2[w];
        }
    }
    __syncthreads();

    // ---- Phase 5: logits = Q @ W, warp per 5 query rows, float4 streams ----
    const float4* Qb = (const float4*)(query + (size_t)b * NQ * DQ);
    for (int g = warp; g < 15; g += 8) {
        int r0 = g * 5;
        float acc[5][5];
        #pragma unroll
        for (int r = 0; r < 5; ++r)
            #pragma unroll
            for (int w = 0; w < 5; ++w) acc[r][w] = 0.f;

        #pragma unroll
        for (int it = 0; it < 5; ++it) {
            int d4 = lane + it * 32;
            float4 qv[5];
            #pragma unroll
            for (int r = 0; r < 5; ++r) qv[r] = __ldcs(&Qb[(r0 + r) * 160 + d4]);
            #pragma unroll
            for (int w = 0; w < 5; ++w) {
                float4 wv = *(const float4*)&WT[w * WS + d4 * 4];
                #pragma unroll
                for (int r = 0; r < 5; ++r) {
                    acc[r][w] = fmaf(qv[r].x, wv.x, acc[r][w]);
                    acc[r][w] = fmaf(qv[r].y, wv.y, acc[r][w]);
                    acc[r][w] = fmaf(qv[r].z, wv.z, acc[r][w]);
                    acc[r][w] = fmaf(qv[r].w, wv.w, acc[r][w]);
                }
            }
        }
        #pragma unroll
        for (int r = 0; r < 5; ++r)
            #pragma unroll
            for (int w = 0; w < 5; ++w) {
                float v = acc[r][w];
                v += __shfl_xor_sync(0xffffffffu, v, 16);
                v += __shfl_xor_sync(0xffffffffu, v, 8);
                v += __shfl_xor_sync(0xffffffffu, v, 4);
                v += __shfl_xor_sync(0xffffffffu, v, 2);
                v += __shfl_xor_sync(0xffffffffu, v, 1);
                acc[r][w] = v;
            }
        if (lane == 0) {
            #pragma unroll
            for (int r = 0; r < 5; ++r)
                #pragma unroll
                for (int w = 0; w < 5; ++w)
                    LOG[(r0 + r) * 5 + w] = acc[r][w];
        }
    }
    __syncthreads();

    // ---- Phase 6: coalesced output store ----
    for (int idx = t; idx < NQ * NWAY; idx += 256)
        out[(size_t)b * (NQ * NWAY) + idx] = LOG[idx];
}

extern "C" void kernel_launch(void* const* d_in, const int* in_sizes, int n_in,
                              void* d_out, int out_size)
{
    const float* query   = (const float*)d_in[0];
    const float* support = (const float*)d_in[1];
    const int* labels    = (const int*)d_in[2];
    float* out = (float*)d_out;

    int tasks = in_sizes[1] / (NS * DQ);   // 2048

    size_t smem = (size_t)SMEM_FLOATS * sizeof(float);
    cudaFuncSetAttribute(r2d2_fused,
                         cudaFuncAttributeMaxDynamicSharedMemorySize, (int)smem);

    r2d2_fused<<<tasks, 256, smem>>>(query, support, labels, out);
}